// round 12
// baseline (speedup 1.0000x reference)
#include <cuda_runtime.h>
#include <cuda_bf16.h>
#include <cstdint>

// Problem constants
#define BB 2048
#define SS 512
#define DD 128
#define HH 64
#define OO 8
#define H4 16
#define EPSF 1e-5f

typedef unsigned long long u64;
typedef unsigned int u32;

#define DI __device__ __forceinline__

// ---- device scratch (static; runtime alloc is forbidden) ----
// xp layout: plain [row][64] fp32, row = b*512 + s   (GEMM output layout)
__device__ __align__(16) float g_xp[(size_t)SS * BB * HH];   // 256 MB
__device__ __align__(16) float g_z1[BB * H4];
__device__ float g_bn1a[HH], g_bn1c[HH];
__device__ float g_part[16][2][H4];

// ============ bf16 hi/lo split helpers =============================
// pack (even, odd) fp32 pair -> bf16x2 hi (low16 = even) and residual lo
DI void split2(float e, float o, u32& hi, u32& lo) {
    u32 h;
    asm("cvt.rn.bf16x2.f32 %0, %1, %2;" : "=r"(h) : "f"(o), "f"(e));
    float he = __uint_as_float(h << 16);
    float ho = __uint_as_float(h & 0xffff0000u);
    float re = e - he;
    float ro = o - ho;
    u32 l;
    asm("cvt.rn.bf16x2.f32 %0, %1, %2;" : "=r"(l) : "f"(ro), "f"(re));
    hi = h; lo = l;
}

// D = A(row) x B(col) + D,  m16n8k16 bf16 -> f32
DI void mma16816(float* c, const u32* a, const u32* b) {
    asm("mma.sync.aligned.m16n8k16.row.col.f32.bf16.bf16.f32 "
        "{%0,%1,%2,%3}, {%4,%5,%6,%7}, {%8,%9}, {%0,%1,%2,%3};"
        : "+f"(c[0]), "+f"(c[1]), "+f"(c[2]), "+f"(c[3])
        : "r"(a[0]), "r"(a[1]), "r"(a[2]), "r"(a[3]), "r"(b[0]), "r"(b[1]));
}

// =====================================================================
// K1: projection via warp-level bf16 split MMA. (unchanged, validated)
// =====================================================================
#define NRT ((BB * SS) / 16)     // 65536 row-tiles
#define PROJ_BLOCKS 296          // 2 CTAs/SM, 1184 warps

__global__ void __launch_bounds__(128, 2) k_proj(
    const float* __restrict__ x, const float* __restrict__ Wih,
    const float* __restrict__ bih, const float* __restrict__ bhh)
{
    const int lane  = threadIdx.x & 31;
    const int warp  = threadIdx.x >> 5;
    const int gw    = blockIdx.x * 4 + warp;        // 0..1183
    const int nhalf = gw & 1;
    const int nbase = nhalf * 32;
    const int l4    = lane & 3;        // pair-column group
    const int lr    = lane >> 2;       // row-in-frag / n-in-frag

    // ---- B fragments: W_ih hi/lo, register resident ----
    u32 bh[4][8][2], bl[4][8][2];
#pragma unroll
    for (int nt = 0; nt < 4; nt++) {
        const int n = nbase + nt * 8 + lr;
        const float* wr = Wih + (size_t)n * DD;
#pragma unroll
        for (int ks = 0; ks < 8; ks++) {
            const int k = ks * 16 + l4 * 2;
            float2 q0 = *(const float2*)(wr + k);
            float2 q1 = *(const float2*)(wr + k + 8);
            split2(q0.x, q0.y, bh[nt][ks][0], bl[nt][ks][0]);
            split2(q1.x, q1.y, bh[nt][ks][1], bl[nt][ks][1]);
        }
    }

    // ---- bias per lane-column ----
    float bc[4][2];
#pragma unroll
    for (int nt = 0; nt < 4; nt++) {
        const int col = nbase + nt * 8 + l4 * 2;
        bc[nt][0] = bih[col]     + bhh[col];
        bc[nt][1] = bih[col + 1] + bhh[col + 1];
    }

    // ---- persistent loop over row-tiles ----
    for (u32 rt = (u32)(gw >> 1); rt < NRT; rt += 592u) {
        const float* xr = x + ((size_t)rt * 16 + lr) * DD + l4 * 2;

        float c[4][4];
#pragma unroll
        for (int nt = 0; nt < 4; nt++) {
            c[nt][0] = bc[nt][0]; c[nt][1] = bc[nt][1];
            c[nt][2] = bc[nt][0]; c[nt][3] = bc[nt][1];
        }

        // one-deep kstep pipeline
        float2 P0 = *(const float2*)(xr);
        float2 P1 = *(const float2*)(xr + 8 * DD);
        float2 P2 = *(const float2*)(xr + 8);
        float2 P3 = *(const float2*)(xr + 8 * DD + 8);

#pragma unroll
        for (int ks = 0; ks < 8; ks++) {
            float2 N0, N1, N2, N3;
            if (ks < 7) {
                const float* xn = xr + (ks + 1) * 16;
                N0 = *(const float2*)(xn);
                N1 = *(const float2*)(xn + 8 * DD);
                N2 = *(const float2*)(xn + 8);
                N3 = *(const float2*)(xn + 8 * DD + 8);
            }
            u32 ah[4], al[4];
            split2(P0.x, P0.y, ah[0], al[0]);
            split2(P1.x, P1.y, ah[1], al[1]);
            split2(P2.x, P2.y, ah[2], al[2]);
            split2(P3.x, P3.y, ah[3], al[3]);

#pragma unroll
            for (int nt = 0; nt < 4; nt++) {
                mma16816(c[nt], ah, bh[nt][ks]);
                mma16816(c[nt], ah, bl[nt][ks]);
                mma16816(c[nt], al, bh[nt][ks]);
            }
            if (ks < 7) { P0 = N0; P1 = N1; P2 = N2; P3 = N3; }
        }

        // epilogue: rows rt*16+lr and +8, cols nbase + nt*8 + l4*2
        float* o0 = g_xp + ((size_t)rt * 16 + lr) * HH + nbase + l4 * 2;
        float* o1 = o0 + 8 * HH;
#pragma unroll
        for (int nt = 0; nt < 4; nt++) {
            *(float2*)(o0 + nt * 8) = make_float2(c[nt][0], c[nt][1]);
            *(float2*)(o1 + nt * 8) = make_float2(c[nt][2], c[nt][3]);
        }
    }
}

// =====================================================================
// K2: recurrence via tensor-core MMA with in-register C->A repack.
// Group = 16 batch rows, 2 warps: warp w owns output cols [w*32, w*32+32)
// = A-frag ksteps {2w, 2w+1} of the NEXT step. Per step:
//   C  = xp (prefetched, bias included)  [cA]  + hh products (chain 4)
//   cB = hl + lh products                       (chain 8)
//   v = relu(cA+cB); split own half to bf16 hi/lo (pure cvt, no shuffles)
//   exchange 16 regs with partner warp via double-buffered SMEM + 1 bar.
// W_hh hi/lo fragments register-resident. 128 blocks x 64 threads.
// =====================================================================
__global__ void __launch_bounds__(64) k_rnn(
    const float* __restrict__ h0, const float* __restrict__ Whh,
    float* __restrict__ dout)
{
    __shared__ u32 xch[2][2][16][32];   // [buf][warp][reg][lane]

    const int lane = threadIdx.x & 31;
    const int w    = threadIdx.x >> 5;      // 0/1
    const int g    = blockIdx.x;            // batch group: rows g*16..+15
    const int l4   = lane & 3;
    const int lr   = lane >> 2;
    const int wbase = w * 32;

    // ---- B fragments: W_hh hi/lo (own 32 cols, all K=64) ----
    u32 bh[4][4][2], bl[4][4][2];
#pragma unroll
    for (int nt = 0; nt < 4; nt++) {
        const int n = wbase + nt * 8 + lr;
        const float* wr = Whh + (size_t)n * HH;
#pragma unroll
        for (int ks = 0; ks < 4; ks++) {
            const int k = ks * 16 + l4 * 2;
            float2 q0 = *(const float2*)(wr + k);
            float2 q1 = *(const float2*)(wr + k + 8);
            split2(q0.x, q0.y, bh[nt][ks][0], bl[nt][ks][0]);
            split2(q1.x, q1.y, bh[nt][ks][1], bl[nt][ks][1]);
        }
    }

    // ---- initial A fragments from h0 (all 4 ksteps) ----
    u32 Ah[4][4], Al[4][4];
    {
        const float* r0 = h0 + (size_t)(g * 16 + lr) * HH;
        const float* r1 = r0 + 8 * HH;
#pragma unroll
        for (int ks = 0; ks < 4; ks++) {
            const int k = ks * 16 + l4 * 2;
            float2 f0 = *(const float2*)(r0 + k);
            float2 f1 = *(const float2*)(r1 + k);
            float2 f2 = *(const float2*)(r0 + k + 8);
            float2 f3 = *(const float2*)(r1 + k + 8);
            split2(f0.x, f0.y, Ah[ks][0], Al[ks][0]);
            split2(f1.x, f1.y, Ah[ks][1], Al[ks][1]);
            split2(f2.x, f2.y, Ah[ks][2], Al[ks][2]);
            split2(f3.x, f3.y, Ah[ks][3], Al[ks][3]);
        }
    }

    // xp base pointers: row b = g*16+lr (and +8), addr = ((b*512 + s)*64 + col)
    const float* xr0 = g_xp + ((size_t)(g * 16 + lr) * SS) * HH + wbase + l4 * 2;
    const float* xr1 = xr0 + (size_t)8 * SS * HH;

    // prefetch xp for s=0
    float2 p0[4], p1[4];
#pragma unroll
    for (int nt = 0; nt < 4; nt++) {
        p0[nt] = *(const float2*)(xr0 + nt * 8);
        p1[nt] = *(const float2*)(xr1 + nt * 8);
    }

    float vv[4][4];

    for (int s = 0; s < SS; s++) {
        // prefetch next step's xp
        float2 q0n[4], q1n[4];
        if (s + 1 < SS) {
            const float* a0 = xr0 + (size_t)(s + 1) * HH;
            const float* a1 = xr1 + (size_t)(s + 1) * HH;
#pragma unroll
            for (int nt = 0; nt < 4; nt++) {
                q0n[nt] = *(const float2*)(a0 + nt * 8);
                q1n[nt] = *(const float2*)(a1 + nt * 8);
            }
        }

        // C init: cA seeded with xp (bias folded in), cB zero
        float cA[4][4], cB[4][4];
#pragma unroll
        for (int nt = 0; nt < 4; nt++) {
            cA[nt][0] = p0[nt].x; cA[nt][1] = p0[nt].y;
            cA[nt][2] = p1[nt].x; cA[nt][3] = p1[nt].y;
            cB[nt][0] = 0.f; cB[nt][1] = 0.f; cB[nt][2] = 0.f; cB[nt][3] = 0.f;
        }

#pragma unroll
        for (int ks = 0; ks < 4; ks++) {
#pragma unroll
            for (int nt = 0; nt < 4; nt++) {
                mma16816(cA[nt], Ah[ks], bh[nt][ks]);
                mma16816(cB[nt], Ah[ks], bl[nt][ks]);
                mma16816(cB[nt], Al[ks], bh[nt][ks]);
            }
        }

        // v = relu(cA + cB)
#pragma unroll
        for (int nt = 0; nt < 4; nt++) {
            vv[nt][0] = fmaxf(cA[nt][0] + cB[nt][0], 0.f);
            vv[nt][1] = fmaxf(cA[nt][1] + cB[nt][1], 0.f);
            vv[nt][2] = fmaxf(cA[nt][2] + cB[nt][2], 0.f);
            vv[nt][3] = fmaxf(cA[nt][3] + cB[nt][3], 0.f);
        }

        // split own half -> A frags for ks = 2w+p  (C->A register repack)
        const int buf = s & 1;
#pragma unroll
        for (int p = 0; p < 2; p++) {
            const int ks = 2 * w + p;
            split2(vv[2*p][0],     vv[2*p][1],     Ah[ks][0], Al[ks][0]);
            split2(vv[2*p][2],     vv[2*p][3],     Ah[ks][1], Al[ks][1]);
            split2(vv[2*p + 1][0], vv[2*p + 1][1], Ah[ks][2], Al[ks][2]);
            split2(vv[2*p + 1][2], vv[2*p + 1][3], Ah[ks][3], Al[ks][3]);
            // store to exchange buffer
#pragma unroll
            for (int r = 0; r < 4; r++) {
                xch[buf][w][p * 4 + r][lane]     = Ah[ks][r];
                xch[buf][w][8 + p * 4 + r][lane] = Al[ks][r];
            }
        }
        __syncthreads();
        // load partner's half
        const int wo = 1 - w;
#pragma unroll
        for (int p = 0; p < 2; p++) {
            const int ks = 2 * wo + p;
#pragma unroll
            for (int r = 0; r < 4; r++) {
                Ah[ks][r] = xch[buf][wo][p * 4 + r][lane];
                Al[ks][r] = xch[buf][wo][8 + p * 4 + r][lane];
            }
        }

#pragma unroll
        for (int nt = 0; nt < 4; nt++) { p0[nt] = q0n[nt]; p1[nt] = q1n[nt]; }
    }

    // hT = last hidden state
    float* hT = dout + (size_t)BB * OO;
    float* o0 = hT + (size_t)(g * 16 + lr) * HH + wbase + l4 * 2;
    float* o1 = o0 + 8 * HH;
#pragma unroll
    for (int nt = 0; nt < 4; nt++) {
        *(float2*)(o0 + nt * 8) = make_float2(vv[nt][0], vv[nt][1]);
        *(float2*)(o1 + nt * 8) = make_float2(vv[nt][2], vv[nt][3]);
    }
}

// =====================================================================
// K3: batchnorm-1 stats, one block per feature, shuffle reduction.
// =====================================================================
__global__ void k_bn1stats(const float* __restrict__ dout,
                           const float* __restrict__ g, const float* __restrict__ bb)
{
    const float* hT = dout + (size_t)BB * OO;
    const int f = blockIdx.x, t = threadIdx.x;
    float s = 0.f, q = 0.f;
    for (int b = t; b < BB; b += 128) {
        float v = hT[(size_t)b * HH + f];
        s += v; q += v * v;
    }
#pragma unroll
    for (int off = 16; off > 0; off >>= 1) {
        s += __shfl_xor_sync(0xffffffffu, s, off);
        q += __shfl_xor_sync(0xffffffffu, q, off);
    }
    __shared__ float ws[4], wq[4];
    if ((t & 31) == 0) { ws[t >> 5] = s; wq[t >> 5] = q; }
    __syncthreads();
    if (t == 0) {
        s = (ws[0] + ws[1]) + (ws[2] + ws[3]);
        q = (wq[0] + wq[1]) + (wq[2] + wq[3]);
        float mu  = s * (1.f / BB);
        float var = q * (1.f / BB) - mu * mu;
        float a   = g[f] * rsqrtf(var + EPSF);
        g_bn1a[f] = a;
        g_bn1c[f] = bb[f] - mu * a;
    }
}

// =====================================================================
// K4: z1 = relu(bn1(hT) @ fc1_W^T + b); bn2 partial stats via shuffles.
// =====================================================================
__global__ void k_fc1(const float* __restrict__ dout,
                      const float* __restrict__ W1, const float* __restrict__ b1f)
{
    const float* hT = dout + (size_t)BB * OO;
    __shared__ float sW[H4 * HH];
    __shared__ float sa[HH], sc[HH], sb[H4];
    __shared__ float wsum[4][H4], wsq[4][H4];
    const int t = threadIdx.x;
    const int lane = t & 31, warp = t >> 5;
    for (int i = t; i < H4 * HH; i += 128) sW[i] = W1[i];
    if (t < HH) { sa[t] = g_bn1a[t]; sc[t] = g_bn1c[t]; }
    if (t < H4) sb[t] = b1f[t];
    __syncthreads();

    const int b = blockIdx.x * 128 + t;
    float y[HH];
    {
        const float4* hp = (const float4*)(hT + (size_t)b * HH);
#pragma unroll
        for (int k = 0; k < 16; k++) {
            float4 u = hp[k];
            y[4*k]   = sa[4*k]   * u.x + sc[4*k];
            y[4*k+1] = sa[4*k+1] * u.y + sc[4*k+1];
            y[4*k+2] = sa[4*k+2] * u.z + sc[4*k+2];
            y[4*k+3] = sa[4*k+3] * u.w + sc[4*k+3];
        }
    }

    float s[H4], q[H4];
    float4* z4 = (float4*)(g_z1 + (size_t)b * H4);
#pragma unroll
    for (int j4 = 0; j4 < 4; j4++) {
        float4 zv;
        float* zp = (float*)&zv;
#pragma unroll
        for (int jj = 0; jj < 4; jj++) {
            int j = j4 * 4 + jj;
            float acc = sb[j];
#pragma unroll
            for (int f = 0; f < HH; f++) acc += sW[j * HH + f] * y[f];
            acc = fmaxf(acc, 0.f);
            zp[jj] = acc;
            s[j] = acc; q[j] = acc * acc;
        }
        z4[j4] = zv;
    }

#pragma unroll
    for (int j = 0; j < H4; j++) {
#pragma unroll
        for (int off = 16; off > 0; off >>= 1) {
            s[j] += __shfl_xor_sync(0xffffffffu, s[j], off);
            q[j] += __shfl_xor_sync(0xffffffffu, q[j], off);
        }
    }
    if (lane == 0) {
#pragma unroll
        for (int j = 0; j < H4; j++) { wsum[warp][j] = s[j]; wsq[warp][j] = q[j]; }
    }
    __syncthreads();
    if (t < H4) {
        g_part[blockIdx.x][0][t] = (wsum[0][t] + wsum[1][t]) + (wsum[2][t] + wsum[3][t]);
        g_part[blockIdx.x][1][t] = (wsq[0][t]  + wsq[1][t])  + (wsq[2][t]  + wsq[3][t]);
    }
}

// =====================================================================
// K5: out = bn2(z1) @ fc2_W^T + b, bn2 coefficients finalized in-block.
// =====================================================================
__global__ void k_fc2(const float* __restrict__ g2, const float* __restrict__ b2,
                      const float* __restrict__ W2, const float* __restrict__ b2f,
                      float* __restrict__ out)
{
    __shared__ float sW[OO * H4], sa[H4], sc[H4], sb[OO];
    const int t = threadIdx.x;
    if (t < H4) {
        float s = 0.f, q = 0.f;
#pragma unroll
        for (int k = 0; k < 16; k++) { s += g_part[k][0][t]; q += g_part[k][1][t]; }
        float mu  = s * (1.f / BB);
        float var = q * (1.f / BB) - mu * mu;
        float a   = g2[t] * rsqrtf(var + EPSF);
        sa[t] = a;
        sc[t] = b2[t] - mu * a;
    }
    sW[t] = W2[t];                 // OO*H4 == 128 == blockDim
    if (t < OO) sb[t] = b2f[t];
    __syncthreads();

    const int b = blockIdx.x * 128 + t;
    float z[H4];
    {
        const float4* zp = (const float4*)(g_z1 + (size_t)b * H4);
#pragma unroll
        for (int k = 0; k < 4; k++) {
            float4 u = zp[k];
            z[4*k]   = sa[4*k]   * u.x + sc[4*k];
            z[4*k+1] = sa[4*k+1] * u.y + sc[4*k+1];
            z[4*k+2] = sa[4*k+2] * u.z + sc[4*k+2];
            z[4*k+3] = sa[4*k+3] * u.w + sc[4*k+3];
        }
    }
#pragma unroll
    for (int o = 0; o < OO; o++) {
        float acc = sb[o];
#pragma unroll
        for (int j = 0; j < H4; j++) acc += sW[o * H4 + j] * z[j];
        out[(size_t)b * OO + o] = acc;
    }
}

// =====================================================================
extern "C" void kernel_launch(void* const* d_in, const int* in_sizes, int n_in,
                              void* d_out, int out_size)
{
    const float* x    = (const float*)d_in[0];
    const float* h0   = (const float*)d_in[1];
    const float* Wih  = (const float*)d_in[2];
    const float* Whh  = (const float*)d_in[3];
    const float* bih  = (const float*)d_in[4];
    const float* bhh  = (const float*)d_in[5];
    const float* bn1g = (const float*)d_in[6];
    const float* bn1b = (const float*)d_in[7];
    const float* fc1W = (const float*)d_in[8];
    const float* fc1b = (const float*)d_in[9];
    const float* bn2g = (const float*)d_in[10];
    const float* bn2b = (const float*)d_in[11];
    const float* fc2W = (const float*)d_in[12];
    const float* fc2b = (const float*)d_in[13];
    float* out = (float*)d_out;

    cudaStream_t s0 = 0;
    k_proj<<<PROJ_BLOCKS, 128, 0, s0>>>(x, Wih, bih, bhh);
    k_rnn<<<128, 64, 0, s0>>>(h0, Whh, out);
    k_bn1stats<<<64, 128, 0, s0>>>(out, bn1g, bn1b);
    k_fc1<<<16, 128, 0, s0>>>(out, fc1W, fc1b);
    k_fc2<<<16, 128, 0, s0>>>(bn2g, bn2b, fc2W, fc2b, out);
}

// round 14
// speedup vs baseline: 1.1685x; 1.1685x over previous
#include <cuda_runtime.h>
#include <cuda_bf16.h>
#include <cstdint>

// Problem constants
#define BB 2048
#define SS 512
#define DD 128
#define HH 64
#define OO 8
#define H4 16
#define EPSF 1e-5f

#define CHUNK 16
#define NCHUNK 32        // SS / CHUNK
#define XPAD 66          // floats per (b,s) row in smem xp buffer
#define NTHR 384         // 8 rnn warps + 4 proj warps

typedef unsigned long long u64;
typedef unsigned int u32;

#define DI __device__ __forceinline__

DI void upk2(u64 v, float& lo, float& hi) {
    asm("mov.b64 {%0, %1}, %2;" : "=f"(lo), "=f"(hi) : "l"(v));
}
DI u64 ffma2(u64 a, u64 b, u64 c) {
    u64 d; asm("fma.rn.f32x2 %0, %1, %2, %3;" : "=l"(d) : "l"(a), "l"(b), "l"(c)); return d;
}

// ---- device scratch ----
__device__ __align__(16) float g_z1[BB * H4];
__device__ float g_bn1a[HH], g_bn1c[HH];
__device__ float g_part[16][2][H4];

// ============ bf16 hi/lo split helpers =============================
DI void split2(float e, float o, u32& hi, u32& lo) {
    u32 h;
    asm("cvt.rn.bf16x2.f32 %0, %1, %2;" : "=r"(h) : "f"(o), "f"(e));
    float he = __uint_as_float(h << 16);
    float ho = __uint_as_float(h & 0xffff0000u);
    float re = e - he;
    float ro = o - ho;
    u32 l;
    asm("cvt.rn.bf16x2.f32 %0, %1, %2;" : "=r"(l) : "f"(ro), "f"(re));
    hi = h; lo = l;
}

DI void mma16816(float* c, const u32* a, u32 b0, u32 b1) {
    asm("mma.sync.aligned.m16n8k16.row.col.f32.bf16.bf16.f32 "
        "{%0,%1,%2,%3}, {%4,%5,%6,%7}, {%8,%9}, {%0,%1,%2,%3};"
        : "+f"(c[0]), "+f"(c[1]), "+f"(c[2]), "+f"(c[3])
        : "r"(a[0]), "r"(a[1]), "r"(a[2]), "r"(a[3]), "r"(b0), "r"(b1));
}

// =====================================================================
// Fused projection + recurrence.
// CTA = one group of 16 batch rows. 384 threads:
//   warps 0..7  : FFMA recurrence (warp owns rows 2w, 2w+1) -- R11 design,
//                 xp read from SMEM chunk buffer.
//   warps 8..11 : MMA projection producing xp chunks (16 steps) into the
//                 double-buffered SMEM chunk (R11 k_proj pattern, B frags
//                 from SMEM table).
// SMEM: xpb [2][16][CHUNK][XPAD] f32   = 135168 B
//       sWf [8][8][32] uint4           =  32768 B   (W_ih hi/lo frags)
//       shh [8][2][2][64] f32          =   8192 B   (h double buffer)
// =====================================================================
#define SM_XPB 0
#define SM_SWF 135168
#define SM_SHH (135168 + 32768)
#define SM_TOTAL (135168 + 32768 + 8192)    // 176128 B

__global__ void __launch_bounds__(NTHR, 1) k_fused(
    const float* __restrict__ x, const float* __restrict__ Wih,
    const float* __restrict__ Whh,
    const float* __restrict__ bih, const float* __restrict__ bhh,
    const float* __restrict__ h0, float* __restrict__ dout)
{
    extern __shared__ char smb[];
    float* xpb = (float*)(smb + SM_XPB);   // [2][16][CHUNK][XPAD]
    uint4* sWf = (uint4*)(smb + SM_SWF);   // [(nt*8+ks)*32+lane], nt 0..7
    float* shh = (float*)(smb + SM_SHH);   // [8][2][2][64]

    const int tid  = threadIdx.x;
    const int wid  = tid >> 5;
    const int lane = tid & 31;
    const int g    = blockIdx.x;
    const int l4   = lane & 3;
    const int lr   = lane >> 2;

    // ---- build W_ih fragment table (all threads): 2048 uint4 = 32 KB ----
    for (int idx = tid; idx < 2048; idx += NTHR) {
        const int ln = idx & 31;
        const int ks = (idx >> 5) & 7;
        const int nt = (idx >> 8) & 7;          // 0..7 (all 64 cols)
        const int n  = nt * 8 + (ln >> 2);
        const int k  = ks * 16 + (ln & 3) * 2;
        const float* wr = Wih + (size_t)n * DD;
        u32 bh0, bl0, bh1, bl1;
        split2(wr[k],     wr[k + 1], bh0, bl0);
        split2(wr[k + 8], wr[k + 9], bh1, bl1);
        sWf[idx] = make_uint4(bh0, bh1, bl0, bl1);
    }

    // ================= per-role setup =================
    u64 w0[32], w1[32];      // rnn warps: W_hh rows in regs
    float bc[8][2];          // proj warps: bias per lane-col

    if (wid < 8) {
        const ulonglong2* p0 = (const ulonglong2*)(Whh + (size_t)lane * HH);
        const ulonglong2* p1 = (const ulonglong2*)(Whh + (size_t)(lane + 32) * HH);
#pragma unroll
        for (int k = 0; k < 16; k++) {
            ulonglong2 a = p0[k]; w0[2 * k] = a.x; w0[2 * k + 1] = a.y;
            ulonglong2 b = p1[k]; w1[2 * k] = b.x; w1[2 * k + 1] = b.y;
        }
        const int b0 = g * 16 + 2 * wid;
        const int b1 = b0 + 1;
        float* s0 = shh + ((wid * 2 + 0) * 2 + 0) * 64;
        float* s1 = shh + ((wid * 2 + 1) * 2 + 0) * 64;
        s0[lane]      = h0[(size_t)b0 * HH + lane];
        s0[lane + 32] = h0[(size_t)b0 * HH + lane + 32];
        s1[lane]      = h0[(size_t)b1 * HH + lane];
        s1[lane + 32] = h0[(size_t)b1 * HH + lane + 32];
    } else {
#pragma unroll
        for (int nt = 0; nt < 8; nt++) {
            const int col = nt * 8 + l4 * 2;
            bc[nt][0] = bih[col]     + bhh[col];
            bc[nt][1] = bih[col + 1] + bhh[col + 1];
        }
    }
    __syncthreads();   // sWf + shh ready

    // ---- proj produce lambda: chunk c -> xpb[dstbuf] ----
    auto produce = [&](int c, int dstbuf) {
        const int p = wid - 8;                 // 0..3
        const int s0i = c * CHUNK;
#pragma unroll
        for (int t = p * 4; t < p * 4 + 4; t++) {
            const int b = g * 16 + t;
            const float* xr = x + ((size_t)b * SS + s0i + lr) * DD + l4 * 2;

            float C[8][4];
#pragma unroll
            for (int nt = 0; nt < 8; nt++) {
                C[nt][0] = bc[nt][0]; C[nt][1] = bc[nt][1];
                C[nt][2] = bc[nt][0]; C[nt][3] = bc[nt][1];
            }

            float2 P0 = *(const float2*)(xr);
            float2 P1 = *(const float2*)(xr + 8 * DD);
            float2 P2 = *(const float2*)(xr + 8);
            float2 P3 = *(const float2*)(xr + 8 * DD + 8);

#pragma unroll
            for (int ks = 0; ks < 8; ks++) {
                float2 N0, N1, N2, N3;
                if (ks < 7) {
                    const float* xn = xr + (ks + 1) * 16;
                    N0 = *(const float2*)(xn);
                    N1 = *(const float2*)(xn + 8 * DD);
                    N2 = *(const float2*)(xn + 8);
                    N3 = *(const float2*)(xn + 8 * DD + 8);
                }
                u32 ah[4], al[4];
                split2(P0.x, P0.y, ah[0], al[0]);
                split2(P1.x, P1.y, ah[1], al[1]);
                split2(P2.x, P2.y, ah[2], al[2]);
                split2(P3.x, P3.y, ah[3], al[3]);

#pragma unroll
                for (int nt = 0; nt < 8; nt++) {
                    uint4 wf = sWf[(nt * 8 + ks) * 32 + lane];
                    mma16816(C[nt], ah, wf.x, wf.y);   // hh
                    mma16816(C[nt], ah, wf.z, wf.w);   // h*l
                    mma16816(C[nt], al, wf.x, wf.y);   // l*h
                }
                if (ks < 7) { P0 = N0; P1 = N1; P2 = N2; P3 = N3; }
            }

            float* d0 = xpb + (size_t)((dstbuf * 16 + t) * CHUNK + lr) * XPAD + l4 * 2;
            float* d1 = d0 + 8 * XPAD;
#pragma unroll
            for (int nt = 0; nt < 8; nt++) {
                *(float2*)(d0 + nt * 8) = make_float2(C[nt][0], C[nt][1]);
                *(float2*)(d1 + nt * 8) = make_float2(C[nt][2], C[nt][3]);
            }
        }
    };

    // prologue: fill chunk 0 into buf 0
    if (wid >= 8) produce(0, 0);
    __syncthreads();

    // ================= main chunk loop =================
    int hbuf = 0;
    float v00 = 0.f, v01 = 0.f, v10 = 0.f, v11 = 0.f;
    const int b0l = 2 * wid, b1l = 2 * wid + 1;   // valid for rnn warps only

    for (int c = 0; c < NCHUNK; c++) {
        const int buf = c & 1;

        if (wid >= 8) {
            if (c + 1 < NCHUNK) produce(c + 1, buf ^ 1);
        } else {
            const float* xpr0 = xpb + (size_t)(buf * 16 + b0l) * CHUNK * XPAD;
            const float* xpr1 = xpb + (size_t)(buf * 16 + b1l) * CHUNK * XPAD;
#pragma unroll 4
            for (int s = 0; s < CHUNK; s++) {
                const float xp00 = xpr0[s * XPAD + lane];
                const float xp01 = xpr0[s * XPAD + lane + 32];
                const float xp10 = xpr1[s * XPAD + lane];
                const float xp11 = xpr1[s * XPAD + lane + 32];

                const ulonglong2* hp0 =
                    (const ulonglong2*)(shh + ((wid * 2 + 0) * 2 + hbuf) * 64);
                const ulonglong2* hp1 =
                    (const ulonglong2*)(shh + ((wid * 2 + 1) * 2 + hbuf) * 64);
                u64 a00 = 0, a01 = 0, a10 = 0, a11 = 0;
#pragma unroll
                for (int k = 0; k < 16; k++) {
                    ulonglong2 q0 = hp0[k];
                    ulonglong2 q1 = hp1[k];
                    a00 = ffma2(w0[2*k], q0.x, a00); a00 = ffma2(w0[2*k+1], q0.y, a00);
                    a01 = ffma2(w1[2*k], q0.x, a01); a01 = ffma2(w1[2*k+1], q0.y, a01);
                    a10 = ffma2(w0[2*k], q1.x, a10); a10 = ffma2(w0[2*k+1], q1.y, a10);
                    a11 = ffma2(w1[2*k], q1.x, a11); a11 = ffma2(w1[2*k+1], q1.y, a11);
                }
                float lo, hi;
                upk2(a00, lo, hi); v00 = fmaxf(lo + hi + xp00, 0.f);
                upk2(a01, lo, hi); v01 = fmaxf(lo + hi + xp01, 0.f);
                upk2(a10, lo, hi); v10 = fmaxf(lo + hi + xp10, 0.f);
                upk2(a11, lo, hi); v11 = fmaxf(lo + hi + xp11, 0.f);

                hbuf ^= 1;
                float* s0p = shh + ((wid * 2 + 0) * 2 + hbuf) * 64;
                float* s1p = shh + ((wid * 2 + 1) * 2 + hbuf) * 64;
                s0p[lane]      = v00;
                s0p[lane + 32] = v01;
                s1p[lane]      = v10;
                s1p[lane + 32] = v11;
                __syncwarp();
            }
        }
        __syncthreads();
    }

    // hT output
    if (wid < 8) {
        float* hT = dout + (size_t)BB * OO;
        const int b0 = g * 16 + b0l, b1 = g * 16 + b1l;
        hT[(size_t)b0 * HH + lane]      = v00;
        hT[(size_t)b0 * HH + lane + 32] = v01;
        hT[(size_t)b1 * HH + lane]      = v10;
        hT[(size_t)b1 * HH + lane + 32] = v11;
    }
}

// =====================================================================
// K3: batchnorm-1 stats, one block per feature, shuffle reduction.
// =====================================================================
__global__ void k_bn1stats(const float* __restrict__ dout,
                           const float* __restrict__ g, const float* __restrict__ bb)
{
    const float* hT = dout + (size_t)BB * OO;
    const int f = blockIdx.x, t = threadIdx.x;
    float s = 0.f, q = 0.f;
    for (int b = t; b < BB; b += 128) {
        float v = hT[(size_t)b * HH + f];
        s += v; q += v * v;
    }
#pragma unroll
    for (int off = 16; off > 0; off >>= 1) {
        s += __shfl_xor_sync(0xffffffffu, s, off);
        q += __shfl_xor_sync(0xffffffffu, q, off);
    }
    __shared__ float ws[4], wq[4];
    if ((t & 31) == 0) { ws[t >> 5] = s; wq[t >> 5] = q; }
    __syncthreads();
    if (t == 0) {
        s = (ws[0] + ws[1]) + (ws[2] + ws[3]);
        q = (wq[0] + wq[1]) + (wq[2] + wq[3]);
        float mu  = s * (1.f / BB);
        float var = q * (1.f / BB) - mu * mu;
        float a   = g[f] * rsqrtf(var + EPSF);
        g_bn1a[f] = a;
        g_bn1c[f] = bb[f] - mu * a;
    }
}

// =====================================================================
// K4: z1 = relu(bn1(hT) @ fc1_W^T + b); bn2 partial stats via shuffles.
// =====================================================================
__global__ void k_fc1(const float* __restrict__ dout,
                      const float* __restrict__ W1, const float* __restrict__ b1f)
{
    const float* hT = dout + (size_t)BB * OO;
    __shared__ float sW[H4 * HH];
    __shared__ float sa[HH], sc[HH], sb[H4];
    __shared__ float wsum[4][H4], wsq[4][H4];
    const int t = threadIdx.x;
    const int lane = t & 31, warp = t >> 5;
    for (int i = t; i < H4 * HH; i += 128) sW[i] = W1[i];
    if (t < HH) { sa[t] = g_bn1a[t]; sc[t] = g_bn1c[t]; }
    if (t < H4) sb[t] = b1f[t];
    __syncthreads();

    const int b = blockIdx.x * 128 + t;
    float y[HH];
    {
        const float4* hp = (const float4*)(hT + (size_t)b * HH);
#pragma unroll
        for (int k = 0; k < 16; k++) {
            float4 u = hp[k];
            y[4*k]   = sa[4*k]   * u.x + sc[4*k];
            y[4*k+1] = sa[4*k+1] * u.y + sc[4*k+1];
            y[4*k+2] = sa[4*k+2] * u.z + sc[4*k+2];
            y[4*k+3] = sa[4*k+3] * u.w + sc[4*k+3];
        }
    }

    float s[H4], q[H4];
    float4* z4 = (float4*)(g_z1 + (size_t)b * H4);
#pragma unroll
    for (int j4 = 0; j4 < 4; j4++) {
        float4 zv;
        float* zp = (float*)&zv;
#pragma unroll
        for (int jj = 0; jj < 4; jj++) {
            int j = j4 * 4 + jj;
            float acc = sb[j];
#pragma unroll
            for (int f = 0; f < HH; f++) acc += sW[j * HH + f] * y[f];
            acc = fmaxf(acc, 0.f);
            zp[jj] = acc;
            s[j] = acc; q[j] = acc * acc;
        }
        z4[j4] = zv;
    }

#pragma unroll
    for (int j = 0; j < H4; j++) {
#pragma unroll
        for (int off = 16; off > 0; off >>= 1) {
            s[j] += __shfl_xor_sync(0xffffffffu, s[j], off);
            q[j] += __shfl_xor_sync(0xffffffffu, q[j], off);
        }
    }
    if (lane == 0) {
#pragma unroll
        for (int j = 0; j < H4; j++) { wsum[warp][j] = s[j]; wsq[warp][j] = q[j]; }
    }
    __syncthreads();
    if (t < H4) {
        g_part[blockIdx.x][0][t] = (wsum[0][t] + wsum[1][t]) + (wsum[2][t] + wsum[3][t]);
        g_part[blockIdx.x][1][t] = (wsq[0][t]  + wsq[1][t])  + (wsq[2][t]  + wsq[3][t]);
    }
}

// =====================================================================
// K5: out = bn2(z1) @ fc2_W^T + b, bn2 coefficients finalized in-block.
// =====================================================================
__global__ void k_fc2(const float* __restrict__ g2, const float* __restrict__ b2,
                      const float* __restrict__ W2, const float* __restrict__ b2f,
                      float* __restrict__ out)
{
    __shared__ float sW[OO * H4], sa[H4], sc[H4], sb[OO];
    const int t = threadIdx.x;
    if (t < H4) {
        float s = 0.f, q = 0.f;
#pragma unroll
        for (int k = 0; k < 16; k++) { s += g_part[k][0][t]; q += g_part[k][1][t]; }
        float mu  = s * (1.f / BB);
        float var = q * (1.f / BB) - mu * mu;
        float a   = g2[t] * rsqrtf(var + EPSF);
        sa[t] = a;
        sc[t] = b2[t] - mu * a;
    }
    sW[t] = W2[t];                 // OO*H4 == 128 == blockDim
    if (t < OO) sb[t] = b2f[t];
    __syncthreads();

    const int b = blockIdx.x * 128 + t;
    float z[H4];
    {
        const float4* zp = (const float4*)(g_z1 + (size_t)b * H4);
#pragma unroll
        for (int k = 0; k < 4; k++) {
            float4 u = zp[k];
            z[4*k]   = sa[4*k]   * u.x + sc[4*k];
            z[4*k+1] = sa[4*k+1] * u.y + sc[4*k+1];
            z[4*k+2] = sa[4*k+2] * u.z + sc[4*k+2];
            z[4*k+3] = sa[4*k+3] * u.w + sc[4*k+3];
        }
    }
#pragma unroll
    for (int o = 0; o < OO; o++) {
        float acc = sb[o];
#pragma unroll
        for (int j = 0; j < H4; j++) acc += sW[o * H4 + j] * z[j];
        out[(size_t)b * OO + o] = acc;
    }
}

// =====================================================================
extern "C" void kernel_launch(void* const* d_in, const int* in_sizes, int n_in,
                              void* d_out, int out_size)
{
    const float* x    = (const float*)d_in[0];
    const float* h0   = (const float*)d_in[1];
    const float* Wih  = (const float*)d_in[2];
    const float* Whh  = (const float*)d_in[3];
    const float* bih  = (const float*)d_in[4];
    const float* bhh  = (const float*)d_in[5];
    const float* bn1g = (const float*)d_in[6];
    const float* bn1b = (const float*)d_in[7];
    const float* fc1W = (const float*)d_in[8];
    const float* fc1b = (const float*)d_in[9];
    const float* bn2g = (const float*)d_in[10];
    const float* bn2b = (const float*)d_in[11];
    const float* fc2W = (const float*)d_in[12];
    const float* fc2b = (const float*)d_in[13];
    float* out = (float*)d_out;

    cudaFuncSetAttribute(k_fused, cudaFuncAttributeMaxDynamicSharedMemorySize, SM_TOTAL);

    cudaStream_t s0 = 0;
    k_fused<<<BB / 16, NTHR, SM_TOTAL, s0>>>(x, Wih, Whh, bih, bhh, h0, out);
    k_bn1stats<<<64, 128, 0, s0>>>(out, bn1g, bn1b);
    k_fc1<<<16, 128, 0, s0>>>(out, fc1W, fc1b);
    k_fc2<<<16, 128, 0, s0>>>(bn2g, bn2b, fc2W, fc2b, out);
}

// round 16
// speedup vs baseline: 1.8212x; 1.5585x over previous
#include <cuda_runtime.h>
#include <cuda_bf16.h>
#include <cstdint>

// Problem constants
#define BB 2048
#define SS 512
#define DD 128
#define HH 64
#define OO 8
#define H4 16
#define EPSF 1e-5f

#define GR 8             // batch rows per CTA
#define CHUNK 16
#define NCHUNK 32        // SS / CHUNK
#define XPAD 66          // floats per (b,s) row in smem xp buffer
#define NTHR 128         // 4 warps, each does proj + rnn

typedef unsigned long long u64;
typedef unsigned int u32;

#define DI __device__ __forceinline__

DI void upk2(u64 v, float& lo, float& hi) {
    asm("mov.b64 {%0, %1}, %2;" : "=f"(lo), "=f"(hi) : "l"(v));
}
DI u64 ffma2(u64 a, u64 b, u64 c) {
    u64 d; asm("fma.rn.f32x2 %0, %1, %2, %3;" : "=l"(d) : "l"(a), "l"(b), "l"(c)); return d;
}

// ---- device scratch ----
__device__ __align__(16) float g_z1[BB * H4];
__device__ float g_bn1a[HH], g_bn1c[HH];
__device__ float g_part[16][2][H4];

// ============ bf16 hi/lo split helpers =============================
DI void split2(float e, float o, u32& hi, u32& lo) {
    u32 h;
    asm("cvt.rn.bf16x2.f32 %0, %1, %2;" : "=r"(h) : "f"(o), "f"(e));
    float he = __uint_as_float(h << 16);
    float ho = __uint_as_float(h & 0xffff0000u);
    float re = e - he;
    float ro = o - ho;
    u32 l;
    asm("cvt.rn.bf16x2.f32 %0, %1, %2;" : "=r"(l) : "f"(ro), "f"(re));
    hi = h; lo = l;
}

DI void mma16816(float* c, const u32* a, u32 b0, u32 b1) {
    asm("mma.sync.aligned.m16n8k16.row.col.f32.bf16.bf16.f32 "
        "{%0,%1,%2,%3}, {%4,%5,%6,%7}, {%8,%9}, {%0,%1,%2,%3};"
        : "+f"(c[0]), "+f"(c[1]), "+f"(c[2]), "+f"(c[3])
        : "r"(a[0]), "r"(a[1]), "r"(a[2]), "r"(a[3]), "r"(b0), "r"(b1));
}

// =====================================================================
// Fused projection + recurrence, merged roles.
// CTA = 8 batch rows, 4 warps, 2 CTAs/SM (grid 256).
// Per chunk (16 steps), EVERY warp:
//   (a) produces 2 proj tiles (its 2 batch rows x 16 steps) for chunk c+1
//       via bf16 hi/lo split MMA into xpb[buf^1]
//   (b) runs FFMA recurrence for its 2 rows on chunk c from xpb[buf]
// Phases are barrier-free within the chunk; one __syncthreads per chunk.
// SMEM: xpb [2][8][CHUNK][XPAD] f32 = 67584 B
//       sWf [8][8][32] uint4       = 32768 B  (W_ih hi/lo frags)
//       shh [4][2][2][64] f32      =  4096 B  (h double buffer)
// =====================================================================
#define SM_XPB 0
#define SM_SWF 67584
#define SM_SHH (67584 + 32768)
#define SM_TOTAL (67584 + 32768 + 4096)   // 104448 B -> 2 CTAs/SM

__global__ void __launch_bounds__(NTHR, 2) k_fused(
    const float* __restrict__ x, const float* __restrict__ Wih,
    const float* __restrict__ Whh,
    const float* __restrict__ bih, const float* __restrict__ bhh,
    const float* __restrict__ h0, float* __restrict__ dout)
{
    extern __shared__ char smb[];
    float* xpb = (float*)(smb + SM_XPB);   // [2][GR][CHUNK][XPAD]
    uint4* sWf = (uint4*)(smb + SM_SWF);   // [(nt*8+ks)*32+lane], nt 0..7
    float* shh = (float*)(smb + SM_SHH);   // [4][2][2][64]

    const int tid  = threadIdx.x;
    const int wid  = tid >> 5;             // 0..3
    const int lane = tid & 31;
    const int g    = blockIdx.x;           // rows g*8 .. g*8+7
    const int l4   = lane & 3;
    const int lr   = lane >> 2;

    // ---- build W_ih fragment table: 2048 uint4 = 32 KB ----
    for (int idx = tid; idx < 2048; idx += NTHR) {
        const int ln = idx & 31;
        const int ks = (idx >> 5) & 7;
        const int nt = (idx >> 8) & 7;
        const int n  = nt * 8 + (ln >> 2);
        const int k  = ks * 16 + (ln & 3) * 2;
        const float* wr = Wih + (size_t)n * DD;
        u32 bh0, bl0, bh1, bl1;
        split2(wr[k],     wr[k + 1], bh0, bl0);
        split2(wr[k + 8], wr[k + 9], bh1, bl1);
        sWf[idx] = make_uint4(bh0, bh1, bl0, bl1);
    }

    // ---- every warp: W_hh rows in regs, bias cols, h0 init ----
    u64 w0[32], w1[32];
    {
        const ulonglong2* p0 = (const ulonglong2*)(Whh + (size_t)lane * HH);
        const ulonglong2* p1 = (const ulonglong2*)(Whh + (size_t)(lane + 32) * HH);
#pragma unroll
        for (int k = 0; k < 16; k++) {
            ulonglong2 a = p0[k]; w0[2 * k] = a.x; w0[2 * k + 1] = a.y;
            ulonglong2 b = p1[k]; w1[2 * k] = b.x; w1[2 * k + 1] = b.y;
        }
    }
    float bc[8][2];
#pragma unroll
    for (int nt = 0; nt < 8; nt++) {
        const int col = nt * 8 + l4 * 2;
        bc[nt][0] = bih[col]     + bhh[col];
        bc[nt][1] = bih[col + 1] + bhh[col + 1];
    }
    {
        const int b0 = g * GR + 2 * wid;
        const int b1 = b0 + 1;
        float* s0 = shh + ((wid * 2 + 0) * 2 + 0) * 64;
        float* s1 = shh + ((wid * 2 + 1) * 2 + 0) * 64;
        s0[lane]      = h0[(size_t)b0 * HH + lane];
        s0[lane + 32] = h0[(size_t)b0 * HH + lane + 32];
        s1[lane]      = h0[(size_t)b1 * HH + lane];
        s1[lane + 32] = h0[(size_t)b1 * HH + lane + 32];
    }

    // ---- produce one tile: batch row (local t), chunk c -> xpb[dstbuf] ----
    auto produce_tile = [&](int t, int c, int dstbuf) {
        const int b = g * GR + t;
        const float* xr = x + ((size_t)b * SS + c * CHUNK + lr) * DD + l4 * 2;

        float C[8][4];
#pragma unroll
        for (int nt = 0; nt < 8; nt++) {
            C[nt][0] = bc[nt][0]; C[nt][1] = bc[nt][1];
            C[nt][2] = bc[nt][0]; C[nt][3] = bc[nt][1];
        }

        // half 0: preload ks 0..3 (16 LDG, MLP=16)
        float2 X[4][4];
#pragma unroll
        for (int h = 0; h < 4; h++) {
            X[h][0] = *(const float2*)(xr + h * 16);
            X[h][1] = *(const float2*)(xr + h * 16 + 8 * DD);
            X[h][2] = *(const float2*)(xr + h * 16 + 8);
            X[h][3] = *(const float2*)(xr + h * 16 + 8 * DD + 8);
        }
#pragma unroll
        for (int ks = 0; ks < 4; ks++) {
            u32 ah[4], al[4];
            split2(X[ks][0].x, X[ks][0].y, ah[0], al[0]);
            split2(X[ks][1].x, X[ks][1].y, ah[1], al[1]);
            split2(X[ks][2].x, X[ks][2].y, ah[2], al[2]);
            split2(X[ks][3].x, X[ks][3].y, ah[3], al[3]);
#pragma unroll
            for (int nt = 0; nt < 8; nt++) {
                uint4 wf = sWf[(nt * 8 + ks) * 32 + lane];
                mma16816(C[nt], ah, wf.x, wf.y);
                mma16816(C[nt], ah, wf.z, wf.w);
                mma16816(C[nt], al, wf.x, wf.y);
            }
        }
        // half 1: ks 4..7
#pragma unroll
        for (int h = 0; h < 4; h++) {
            X[h][0] = *(const float2*)(xr + (h + 4) * 16);
            X[h][1] = *(const float2*)(xr + (h + 4) * 16 + 8 * DD);
            X[h][2] = *(const float2*)(xr + (h + 4) * 16 + 8);
            X[h][3] = *(const float2*)(xr + (h + 4) * 16 + 8 * DD + 8);
        }
#pragma unroll
        for (int ks = 0; ks < 4; ks++) {
            u32 ah[4], al[4];
            split2(X[ks][0].x, X[ks][0].y, ah[0], al[0]);
            split2(X[ks][1].x, X[ks][1].y, ah[1], al[1]);
            split2(X[ks][2].x, X[ks][2].y, ah[2], al[2]);
            split2(X[ks][3].x, X[ks][3].y, ah[3], al[3]);
#pragma unroll
            for (int nt = 0; nt < 8; nt++) {
                uint4 wf = sWf[(nt * 8 + (ks + 4)) * 32 + lane];
                mma16816(C[nt], ah, wf.x, wf.y);
                mma16816(C[nt], ah, wf.z, wf.w);
                mma16816(C[nt], al, wf.x, wf.y);
            }
        }

        float* d0 = xpb + (size_t)((dstbuf * GR + t) * CHUNK + lr) * XPAD + l4 * 2;
        float* d1 = d0 + 8 * XPAD;
#pragma unroll
        for (int nt = 0; nt < 8; nt++) {
            *(float2*)(d0 + nt * 8) = make_float2(C[nt][0], C[nt][1]);
            *(float2*)(d1 + nt * 8) = make_float2(C[nt][2], C[nt][3]);
        }
    };

    // prologue: fill chunk 0 into buf 0
    produce_tile(2 * wid,     0, 0);
    produce_tile(2 * wid + 1, 0, 0);
    __syncthreads();

    // ================= main chunk loop =================
    int hbuf = 0;
    float v00 = 0.f, v01 = 0.f, v10 = 0.f, v11 = 0.f;
    const int b0l = 2 * wid, b1l = 2 * wid + 1;

    for (int c = 0; c < NCHUNK; c++) {
        const int buf = c & 1;

        // (a) produce chunk c+1
        if (c + 1 < NCHUNK) {
            produce_tile(b0l, c + 1, buf ^ 1);
            produce_tile(b1l, c + 1, buf ^ 1);
        }

        // (b) recurrence on chunk c
        {
            const float* xpr0 = xpb + (size_t)(buf * GR + b0l) * CHUNK * XPAD;
            const float* xpr1 = xpb + (size_t)(buf * GR + b1l) * CHUNK * XPAD;
#pragma unroll 4
            for (int s = 0; s < CHUNK; s++) {
                const float xp00 = xpr0[s * XPAD + lane];
                const float xp01 = xpr0[s * XPAD + lane + 32];
                const float xp10 = xpr1[s * XPAD + lane];
                const float xp11 = xpr1[s * XPAD + lane + 32];

                const ulonglong2* hp0 =
                    (const ulonglong2*)(shh + ((wid * 2 + 0) * 2 + hbuf) * 64);
                const ulonglong2* hp1 =
                    (const ulonglong2*)(shh + ((wid * 2 + 1) * 2 + hbuf) * 64);
                u64 a00 = 0, a01 = 0, a10 = 0, a11 = 0;
#pragma unroll
                for (int k = 0; k < 16; k++) {
                    ulonglong2 q0 = hp0[k];
                    ulonglong2 q1 = hp1[k];
                    a00 = ffma2(w0[2*k], q0.x, a00); a00 = ffma2(w0[2*k+1], q0.y, a00);
                    a01 = ffma2(w1[2*k], q0.x, a01); a01 = ffma2(w1[2*k+1], q0.y, a01);
                    a10 = ffma2(w0[2*k], q1.x, a10); a10 = ffma2(w0[2*k+1], q1.y, a10);
                    a11 = ffma2(w1[2*k], q1.x, a11); a11 = ffma2(w1[2*k+1], q1.y, a11);
                }
                float lo, hi;
                upk2(a00, lo, hi); v00 = fmaxf(lo + hi + xp00, 0.f);
                upk2(a01, lo, hi); v01 = fmaxf(lo + hi + xp01, 0.f);
                upk2(a10, lo, hi); v10 = fmaxf(lo + hi + xp10, 0.f);
                upk2(a11, lo, hi); v11 = fmaxf(lo + hi + xp11, 0.f);

                hbuf ^= 1;
                float* s0p = shh + ((wid * 2 + 0) * 2 + hbuf) * 64;
                float* s1p = shh + ((wid * 2 + 1) * 2 + hbuf) * 64;
                s0p[lane]      = v00;
                s0p[lane + 32] = v01;
                s1p[lane]      = v10;
                s1p[lane + 32] = v11;
                __syncwarp();
            }
        }
        __syncthreads();
    }

    // hT output
    {
        float* hT = dout + (size_t)BB * OO;
        const int b0 = g * GR + b0l, b1 = g * GR + b1l;
        hT[(size_t)b0 * HH + lane]      = v00;
        hT[(size_t)b0 * HH + lane + 32] = v01;
        hT[(size_t)b1 * HH + lane]      = v10;
        hT[(size_t)b1 * HH + lane + 32] = v11;
    }
}

// =====================================================================
// K3: batchnorm-1 stats, one block per feature, shuffle reduction.
// =====================================================================
__global__ void k_bn1stats(const float* __restrict__ dout,
                           const float* __restrict__ g, const float* __restrict__ bb)
{
    const float* hT = dout + (size_t)BB * OO;
    const int f = blockIdx.x, t = threadIdx.x;
    float s = 0.f, q = 0.f;
    for (int b = t; b < BB; b += 128) {
        float v = hT[(size_t)b * HH + f];
        s += v; q += v * v;
    }
#pragma unroll
    for (int off = 16; off > 0; off >>= 1) {
        s += __shfl_xor_sync(0xffffffffu, s, off);
        q += __shfl_xor_sync(0xffffffffu, q, off);
    }
    __shared__ float ws[4], wq[4];
    if ((t & 31) == 0) { ws[t >> 5] = s; wq[t >> 5] = q; }
    __syncthreads();
    if (t == 0) {
        s = (ws[0] + ws[1]) + (ws[2] + ws[3]);
        q = (wq[0] + wq[1]) + (wq[2] + wq[3]);
        float mu  = s * (1.f / BB);
        float var = q * (1.f / BB) - mu * mu;
        float a   = g[f] * rsqrtf(var + EPSF);
        g_bn1a[f] = a;
        g_bn1c[f] = bb[f] - mu * a;
    }
}

// =====================================================================
// K4: z1 = relu(bn1(hT) @ fc1_W^T + b); bn2 partial stats via shuffles.
// =====================================================================
__global__ void k_fc1(const float* __restrict__ dout,
                      const float* __restrict__ W1, const float* __restrict__ b1f)
{
    const float* hT = dout + (size_t)BB * OO;
    __shared__ float sW[H4 * HH];
    __shared__ float sa[HH], sc[HH], sb[H4];
    __shared__ float wsum[4][H4], wsq[4][H4];
    const int t = threadIdx.x;
    const int lane = t & 31, warp = t >> 5;
    for (int i = t; i < H4 * HH; i += 128) sW[i] = W1[i];
    if (t < HH) { sa[t] = g_bn1a[t]; sc[t] = g_bn1c[t]; }
    if (t < H4) sb[t] = b1f[t];
    __syncthreads();

    const int b = blockIdx.x * 128 + t;
    float y[HH];
    {
        const float4* hp = (const float4*)(hT + (size_t)b * HH);
#pragma unroll
        for (int k = 0; k < 16; k++) {
            float4 u = hp[k];
            y[4*k]   = sa[4*k]   * u.x + sc[4*k];
            y[4*k+1] = sa[4*k+1] * u.y + sc[4*k+1];
            y[4*k+2] = sa[4*k+2] * u.z + sc[4*k+2];
            y[4*k+3] = sa[4*k+3] * u.w + sc[4*k+3];
        }
    }

    float s[H4], q[H4];
    float4* z4 = (float4*)(g_z1 + (size_t)b * H4);
#pragma unroll
    for (int j4 = 0; j4 < 4; j4++) {
        float4 zv;
        float* zp = (float*)&zv;
#pragma unroll
        for (int jj = 0; jj < 4; jj++) {
            int j = j4 * 4 + jj;
            float acc = sb[j];
#pragma unroll
            for (int f = 0; f < HH; f++) acc += sW[j * HH + f] * y[f];
            acc = fmaxf(acc, 0.f);
            zp[jj] = acc;
            s[j] = acc; q[j] = acc * acc;
        }
        z4[j4] = zv;
    }

#pragma unroll
    for (int j = 0; j < H4; j++) {
#pragma unroll
        for (int off = 16; off > 0; off >>= 1) {
            s[j] += __shfl_xor_sync(0xffffffffu, s[j], off);
            q[j] += __shfl_xor_sync(0xffffffffu, q[j], off);
        }
    }
    if (lane == 0) {
#pragma unroll
        for (int j = 0; j < H4; j++) { wsum[warp][j] = s[j]; wsq[warp][j] = q[j]; }
    }
    __syncthreads();
    if (t < H4) {
        g_part[blockIdx.x][0][t] = (wsum[0][t] + wsum[1][t]) + (wsum[2][t] + wsum[3][t]);
        g_part[blockIdx.x][1][t] = (wsq[0][t]  + wsq[1][t])  + (wsq[2][t]  + wsq[3][t]);
    }
}

// =====================================================================
// K5: out = bn2(z1) @ fc2_W^T + b, bn2 coefficients finalized in-block.
// =====================================================================
__global__ void k_fc2(const float* __restrict__ g2, const float* __restrict__ b2,
                      const float* __restrict__ W2, const float* __restrict__ b2f,
                      float* __restrict__ out)
{
    __shared__ float sW[OO * H4], sa[H4], sc[H4], sb[OO];
    const int t = threadIdx.x;
    if (t < H4) {
        float s = 0.f, q = 0.f;
#pragma unroll
        for (int k = 0; k < 16; k++) { s += g_part[k][0][t]; q += g_part[k][1][t]; }
        float mu  = s * (1.f / BB);
        float var = q * (1.f / BB) - mu * mu;
        float a   = g2[t] * rsqrtf(var + EPSF);
        sa[t] = a;
        sc[t] = b2[t] - mu * a;
    }
    sW[t] = W2[t];                 // OO*H4 == 128 == blockDim
    if (t < OO) sb[t] = b2f[t];
    __syncthreads();

    const int b = blockIdx.x * 128 + t;
    float z[H4];
    {
        const float4* zp = (const float4*)(g_z1 + (size_t)b * H4);
#pragma unroll
        for (int k = 0; k < 4; k++) {
            float4 u = zp[k];
            z[4*k]   = sa[4*k]   * u.x + sc[4*k];
            z[4*k+1] = sa[4*k+1] * u.y + sc[4*k+1];
            z[4*k+2] = sa[4*k+2] * u.z + sc[4*k+2];
            z[4*k+3] = sa[4*k+3] * u.w + sc[4*k+3];
        }
    }
#pragma unroll
    for (int o = 0; o < OO; o++) {
        float acc = sb[o];
#pragma unroll
        for (int j = 0; j < H4; j++) acc += sW[o * H4 + j] * z[j];
        out[(size_t)b * OO + o] = acc;
    }
}

// =====================================================================
extern "C" void kernel_launch(void* const* d_in, const int* in_sizes, int n_in,
                              void* d_out, int out_size)
{
    const float* x    = (const float*)d_in[0];
    const float* h0   = (const float*)d_in[1];
    const float* Wih  = (const float*)d_in[2];
    const float* Whh  = (const float*)d_in[3];
    const float* bih  = (const float*)d_in[4];
    const float* bhh  = (const float*)d_in[5];
    const float* bn1g = (const float*)d_in[6];
    const float* bn1b = (const float*)d_in[7];
    const float* fc1W = (const float*)d_in[8];
    const float* fc1b = (const float*)d_in[9];
    const float* bn2g = (const float*)d_in[10];
    const float* bn2b = (const float*)d_in[11];
    const float* fc2W = (const float*)d_in[12];
    const float* fc2b = (const float*)d_in[13];
    float* out = (float*)d_out;

    cudaFuncSetAttribute(k_fused, cudaFuncAttributeMaxDynamicSharedMemorySize, SM_TOTAL);

    cudaStream_t s0 = 0;
    k_fused<<<BB / GR, NTHR, SM_TOTAL, s0>>>(x, Wih, Whh, bih, bhh, h0, out);
    k_bn1stats<<<64, 128, 0, s0>>>(out, bn1g, bn1b);
    k_fc1<<<16, 128, 0, s0>>>(out, fc1W, fc1b);
    k_fc2<<<16, 128, 0, s0>>>(bn2g, bn2b, fc2W, fc2b, out);
}